// round 16
// baseline (speedup 1.0000x reference)
#include <cuda_runtime.h>

// AudioOnlySpecAugment: out = concat(V, Aud * keep)
//   X: (32, 2048, 1536) fp32. V = X[..., :256] copied, Aud = X[..., 256:] masked.
// Single fused kernel (measured optimum): thread 0 per block derives the
// per-batch mask windows (L1-resident scalar loads), broadcast via shared;
// body is a pure streaming copy+mask with 4 rows per block.
// Reads are skipped for time-masked rows AND fully freq-masked lanes (output is
// zero there either way; X is finite so v*0 == 0 matches the reference product).
//
// Measured: 112.5-113.2 us total (main kernel ~107 us, 6.86 TB/s effective,
// ~98% of the practical mixed-stream HBM wall). Champion across 3 reruns.

#define B_N 32
#define T_N 2048
#define D_N 1536
#define A_N 1280
#define V_N 256
#define ROW_F4 (D_N / 4)   // 384 float4 per row
#define RPB 4              // rows per block (2048 % 4 == 0 -> same batch within block)

__global__ __launch_bounds__(ROW_F4) void spec_aug_kernel(
    const float4* __restrict__ X,
    const int*    __restrict__ len_words,  // raw 32-bit words (int32 or int64 storage)
    const float*  __restrict__ u_t,
    const float*  __restrict__ u_t0,
    const float*  __restrict__ u_f,
    const float*  __restrict__ u_f0,
    float4*       __restrict__ out)
{
    __shared__ int s_p[8];   // t0a,t1a,t0b,t1b, f0a,f1a,f0b,f1b

    const int row0 = blockIdx.x * RPB;      // first row of this block
    const int b    = row0 >> 11;            // all RPB rows share this batch
    const int t0r  = row0 & (T_N - 1);      // t of first row
    const int tid  = threadIdx.x;

    if (tid == 0) {
        // dtype detection for `lengths`: values in [0,2048). int64-LE storage
        // => every odd 32-bit word is 0; int32 => odd words ~surely nonzero
        // (P[all 4 zero] ~ 6e-14). Words 1..15 in-bounds for both layouts.
        int odd_or = 0;
        #pragma unroll
        for (int i = 1; i < 16; i += 2) odd_or |= len_words[i];
        const int len = (odd_or == 0) ? len_words[2 * b] : len_words[b];

        // Time windows (NT=2), replicating reference f32 arithmetic exactly:
        //   max_t = floor(len*0.2f); t_i = floor(u_t*(max_t+1));
        //   rem = len - t_i; t0 = rem<=0 ? 0 : floor(u_t0*(rem+1))
        const float maxt = floorf((float)len * 0.2f);
        #pragma unroll
        for (int i = 0; i < 2; i++) {
            const int ti  = (int)floorf(u_t[i * B_N + b] * (maxt + 1.0f));
            const int rem = len - ti;
            const int t0  = (rem <= 0) ? 0
                            : (int)floorf(u_t0[i * B_N + b] * ((float)rem + 1.0f));
            s_p[2 * i]     = t0;
            s_p[2 * i + 1] = t0 + ti;
        }

        // Freq windows (NF=2): max_f = int(1280*0.15) = 192.
        //   f = floor(u_f*193); f0_max = max(1280-f,0); f0 = floor(u_f0*(f0_max+1))
        #pragma unroll
        for (int j = 0; j < 2; j++) {
            const int f     = (int)floorf(u_f[j * B_N + b] * 193.0f);
            int       f0max = A_N - f; if (f0max < 0) f0max = 0;
            const int f0 = (int)floorf(u_f0[j * B_N + b] * ((float)f0max + 1.0f));
            s_p[4 + 2 * j]     = f0;
            s_p[4 + 2 * j + 1] = f0 + f;
        }
    }
    __syncthreads();

    const int4 tw = *reinterpret_cast<const int4*>(&s_p[0]);
    const int4 fw = *reinterpret_cast<const int4*>(&s_p[4]);

    const int d   = tid * 4;                // feature offset of this float4
    const bool isV = (d < V_N);

    // Per-lane freq keep multiplier (row-invariant). V region: keep = 1.
    float4 keep;
    {
        const int f = d - V_N;
        float* kp = reinterpret_cast<float*>(&keep);
        #pragma unroll
        for (int c = 0; c < 4; c++) {
            const int fc = f + c;
            const bool m = !isV &&
                ((fc >= fw.x && fc < fw.y) || (fc >= fw.z && fc < fw.w));
            kp[c] = m ? 0.0f : 1.0f;
        }
    }
    // Lane fully freq-masked -> its 32B sector is never needed.
    const bool kz = (keep.x == 0.0f) & (keep.y == 0.0f) &
                    (keep.z == 0.0f) & (keep.w == 0.0f);

    // Per-row time mask: masked rows (audio lanes) write zeros, skip the read.
    bool zrow[RPB];
    #pragma unroll
    for (int rr = 0; rr < RPB; rr++) {
        const int t = t0r + rr;
        zrow[rr] = !isV && ((t >= tw.x && t < tw.y) || (t >= tw.z && t < tw.w));
    }

    const float4* ip = X   + (size_t)row0 * ROW_F4 + tid;
    float4*       op = out + (size_t)row0 * ROW_F4 + tid;

    // Load-all: issue the needed LDG.128 back-to-back for max MLP.
    float4 v[RPB];
    #pragma unroll
    for (int rr = 0; rr < RPB; rr++) {
        if (!zrow[rr] && !kz) v[rr] = __ldcs(ip + rr * ROW_F4);
    }

    // Mask + store-all.
    #pragma unroll
    for (int rr = 0; rr < RPB; rr++) {
        float4 w;
        if (zrow[rr] || kz) {
            w = make_float4(0.f, 0.f, 0.f, 0.f);
        } else {
            w.x = v[rr].x * keep.x;
            w.y = v[rr].y * keep.y;
            w.z = v[rr].z * keep.z;
            w.w = v[rr].w * keep.w;
        }
        __stcs(op + rr * ROW_F4, w);
    }
}

extern "C" void kernel_launch(void* const* d_in, const int* in_sizes, int n_in,
                              void* d_out, int out_size)
{
    const float4* X    = (const float4*)d_in[0];
    const int*    lenw = (const int*)   d_in[1];
    const float*  u_t  = (const float*) d_in[2];
    const float*  u_t0 = (const float*) d_in[3];
    const float*  u_f  = (const float*) d_in[4];
    const float*  u_f0 = (const float*) d_in[5];
    float4*       out  = (float4*)      d_out;

    spec_aug_kernel<<<(B_N * T_N) / RPB, ROW_F4>>>(X, lenw, u_t, u_t0, u_f, u_f0, out);
}

// round 17
// speedup vs baseline: 1.0026x; 1.0026x over previous
#include <cuda_runtime.h>

// AudioOnlySpecAugment: out = concat(V, Aud * keep)
//   X: (32, 2048, 1536) fp32. V = X[..., :256] copied, Aud = X[..., 256:] masked.
// Single fused kernel (measured optimum): thread 0 per block derives the
// per-batch mask windows (L1-resident scalar loads), broadcast via shared;
// body is a pure streaming copy+mask with 4 rows per block.
// Reads are skipped for time-masked rows AND fully freq-masked lanes (output is
// zero there either way; X is finite so v*0 == 0 matches the reference product).
//
// Measured: 112.5-113.2 us total across 4 runs (main kernel ~107 us,
// 6.86 TB/s effective, ~98% of the practical mixed-stream HBM wall).

#define B_N 32
#define T_N 2048
#define D_N 1536
#define A_N 1280
#define V_N 256
#define ROW_F4 (D_N / 4)   // 384 float4 per row
#define RPB 4              // rows per block (2048 % 4 == 0 -> same batch within block)

__global__ __launch_bounds__(ROW_F4) void spec_aug_kernel(
    const float4* __restrict__ X,
    const int*    __restrict__ len_words,  // raw 32-bit words (int32 or int64 storage)
    const float*  __restrict__ u_t,
    const float*  __restrict__ u_t0,
    const float*  __restrict__ u_f,
    const float*  __restrict__ u_f0,
    float4*       __restrict__ out)
{
    __shared__ int s_p[8];   // t0a,t1a,t0b,t1b, f0a,f1a,f0b,f1b

    const int row0 = blockIdx.x * RPB;      // first row of this block
    const int b    = row0 >> 11;            // all RPB rows share this batch
    const int t0r  = row0 & (T_N - 1);      // t of first row
    const int tid  = threadIdx.x;

    if (tid == 0) {
        // dtype detection for `lengths`: values in [0,2048). int64-LE storage
        // => every odd 32-bit word is 0; int32 => odd words ~surely nonzero
        // (P[all 4 zero] ~ 6e-14). Words 1..15 in-bounds for both layouts.
        int odd_or = 0;
        #pragma unroll
        for (int i = 1; i < 16; i += 2) odd_or |= len_words[i];
        const int len = (odd_or == 0) ? len_words[2 * b] : len_words[b];

        // Time windows (NT=2), replicating reference f32 arithmetic exactly:
        //   max_t = floor(len*0.2f); t_i = floor(u_t*(max_t+1));
        //   rem = len - t_i; t0 = rem<=0 ? 0 : floor(u_t0*(rem+1))
        const float maxt = floorf((float)len * 0.2f);
        #pragma unroll
        for (int i = 0; i < 2; i++) {
            const int ti  = (int)floorf(u_t[i * B_N + b] * (maxt + 1.0f));
            const int rem = len - ti;
            const int t0  = (rem <= 0) ? 0
                            : (int)floorf(u_t0[i * B_N + b] * ((float)rem + 1.0f));
            s_p[2 * i]     = t0;
            s_p[2 * i + 1] = t0 + ti;
        }

        // Freq windows (NF=2): max_f = int(1280*0.15) = 192.
        //   f = floor(u_f*193); f0_max = max(1280-f,0); f0 = floor(u_f0*(f0_max+1))
        #pragma unroll
        for (int j = 0; j < 2; j++) {
            const int f     = (int)floorf(u_f[j * B_N + b] * 193.0f);
            int       f0max = A_N - f; if (f0max < 0) f0max = 0;
            const int f0 = (int)floorf(u_f0[j * B_N + b] * ((float)f0max + 1.0f));
            s_p[4 + 2 * j]     = f0;
            s_p[4 + 2 * j + 1] = f0 + f;
        }
    }
    __syncthreads();

    const int4 tw = *reinterpret_cast<const int4*>(&s_p[0]);
    const int4 fw = *reinterpret_cast<const int4*>(&s_p[4]);

    const int d   = tid * 4;                // feature offset of this float4
    const bool isV = (d < V_N);

    // Per-lane freq keep multiplier (row-invariant). V region: keep = 1.
    float4 keep;
    {
        const int f = d - V_N;
        float* kp = reinterpret_cast<float*>(&keep);
        #pragma unroll
        for (int c = 0; c < 4; c++) {
            const int fc = f + c;
            const bool m = !isV &&
                ((fc >= fw.x && fc < fw.y) || (fc >= fw.z && fc < fw.w));
            kp[c] = m ? 0.0f : 1.0f;
        }
    }
    // Lane fully freq-masked -> its 32B sector is never needed.
    const bool kz = (keep.x == 0.0f) & (keep.y == 0.0f) &
                    (keep.z == 0.0f) & (keep.w == 0.0f);

    // Per-row time mask: masked rows (audio lanes) write zeros, skip the read.
    bool zrow[RPB];
    #pragma unroll
    for (int rr = 0; rr < RPB; rr++) {
        const int t = t0r + rr;
        zrow[rr] = !isV && ((t >= tw.x && t < tw.y) || (t >= tw.z && t < tw.w));
    }

    const float4* ip = X   + (size_t)row0 * ROW_F4 + tid;
    float4*       op = out + (size_t)row0 * ROW_F4 + tid;

    // Load-all: issue the needed LDG.128 back-to-back for max MLP.
    float4 v[RPB];
    #pragma unroll
    for (int rr = 0; rr < RPB; rr++) {
        if (!zrow[rr] && !kz) v[rr] = __ldcs(ip + rr * ROW_F4);
    }

    // Mask + store-all.
    #pragma unroll
    for (int rr = 0; rr < RPB; rr++) {
        float4 w;
        if (zrow[rr] || kz) {
            w = make_float4(0.f, 0.f, 0.f, 0.f);
        } else {
            w.x = v[rr].x * keep.x;
            w.y = v[rr].y * keep.y;
            w.z = v[rr].z * keep.z;
            w.w = v[rr].w * keep.w;
        }
        __stcs(op + rr * ROW_F4, w);
    }
}

extern "C" void kernel_launch(void* const* d_in, const int* in_sizes, int n_in,
                              void* d_out, int out_size)
{
    const float4* X    = (const float4*)d_in[0];
    const int*    lenw = (const int*)   d_in[1];
    const float*  u_t  = (const float*) d_in[2];
    const float*  u_t0 = (const float*) d_in[3];
    const float*  u_f  = (const float*) d_in[4];
    const float*  u_f0 = (const float*) d_in[5];
    float4*       out  = (float4*)      d_out;

    spec_aug_kernel<<<(B_N * T_N) / RPB, ROW_F4>>>(X, lenw, u_t, u_t0, u_f, u_f0, out);
}